// round 13
// baseline (speedup 1.0000x reference)
#include <cuda_runtime.h>

// Problem constants (fixed shapes from reference setup_inputs)
#define NB 2
#define NS 4
#define NTIME 256
#define NRECV 64
#define NPROB (NB*NS*NRECV)   // 512 independent sinkhorn problems
#define NPTS  256             // points per cloud
#define NSTEPS 24

#define LOG2E_F 1.4426950408889634f
#define LN2_F   0.6931471805599453f
#define DT_F    0.001f
#define EPSMIN_F 1e-4f        // BLUR^2
#define RATIO_F 0.25f         // SCALING^2

__device__ float g_div[NPROB];          // per-problem divergence
__device__ unsigned int g_done = 0;     // last-block ticket (reset every launch)

__device__ __forceinline__ float ex2f(float x){ float y; asm("ex2.approx.ftz.f32 %0, %1;" : "=f"(y) : "f"(x)); return y; }
__device__ __forceinline__ float lg2f(float x){ float y; asm("lg2.approx.ftz.f32 %0, %1;" : "=f"(y) : "f"(x)); return y; }
// a*1.0 + c : FFMA with immediate multiplier (rt=1 form); rounding identical to FADD
__device__ __forceinline__ float fmai1(float a, float c){ float d; asm("fma.rn.f32 %0, %1, 0f3F800000, %2;" : "=f"(d) : "f"(a), "f"(c)); return d; }

struct SinkSmem {
    alignas(16) float2 hp[NPTS];   // (y_j, T_j) per column; 16B-aligned for LDS.128
    float  xo[NPTS];   // obs amplitudes
    float  xs[NPTS];   // syn amplitudes
    float  F[NPTS], G[NPTS], PX[NPTS], PY[NPTS];
    float  red[32];
};

__device__ __forceinline__ float warpSum(float v){
    #pragma unroll
    for (int o = 16; o; o >>= 1) v += __shfl_xor_sync(0xffffffffu, v, o);
    return v;
}
__device__ __forceinline__ float warpMax(float v){
    #pragma unroll
    for (int o = 16; o; o >>= 1) v = fmaxf(v, __shfl_xor_sync(0xffffffffu, v, o));
    return v;
}
__device__ __forceinline__ float warpMin(float v){
    #pragma unroll
    for (int o = 16; o; o >>= 1) v = fminf(v, __shfl_xor_sync(0xffffffffu, v, o));
    return v;
}

__device__ __forceinline__ float blockSum(float v, float* red){
    v = warpSum(v);
    int w = threadIdx.x >> 5, l = threadIdx.x & 31;
    if (l == 0) red[w] = v;
    __syncthreads();
    if (w == 0) {
        float t = (l < 8) ? red[l] : 0.f;
        t = warpSum(t);
        if (l == 0) red[0] = t;
    }
    __syncthreads();
    v = red[0];
    __syncthreads();
    return v;
}
__device__ __forceinline__ float blockMax(float v, float* red){
    v = warpMax(v);
    int w = threadIdx.x >> 5, l = threadIdx.x & 31;
    if (l == 0) red[w] = v;
    __syncthreads();
    if (w == 0) {
        float t = (l < 8) ? red[l] : -3.4e38f;
        t = warpMax(t);
        if (l == 0) red[0] = t;
    }
    __syncthreads();
    v = red[0];
    __syncthreads();
    return v;
}
__device__ __forceinline__ float blockMin(float v, float* red){
    v = warpMin(v);
    int w = threadIdx.x >> 5, l = threadIdx.x & 31;
    if (l == 0) red[w] = v;
    __syncthreads();
    if (w == 0) {
        float t = (l < 8) ? red[l] : 3.4e38f;
        t = warpMin(t);
        if (l == 0) red[0] = t;
    }
    __syncthreads();
    v = red[0];
    __syncthreads();
    return v;
}

// softmin over 256 columns, log2 domain:
// A_ij = la2 + pot_j*ie2 - ie2*(0.5(ti-tj)^2 + 0.5(xi-yj)^2)
//      = T_j + xsc*y_j + u*j + C_i
//   T_j (smem float2 with y_j), xsc = xi*ie2, u = 2*c2*i
//   u*j carried in 8 rolling registers du[k] (pass 2 also folds -m into them);
//   per-row consts C_i fold back as +0.5*||X_i||^2 in the result.
__device__ __forceinline__ float softmin256(
    const float* __restrict__ pot, const float* __restrict__ yc,
    SinkSmem& sm,
    float xi, float ie2, float c2, float eps, float la2)
{
    const int tid = threadIdx.x;
    __syncthreads();  // previous users of hp are done
    {
        float yv = yc[tid];
        float jv = (float)tid;
        float t  = la2 + pot[tid]*ie2 - (0.5f*yv*yv)*ie2 - c2*jv*jv;
        sm.hp[tid] = make_float2(yv, t);
    }
    __syncthreads();

    const float xsc = xi * ie2;
    const float u   = 2.0f * c2 * (float)tid;
    const float u8  = 8.0f * u;
    const float4* __restrict__ H4 = (const float4*)sm.hp;  // (y0,T0,y1,T1) per entry

    float du[8];
    #pragma unroll
    for (int k = 0; k < 8; k++) du[k] = u * (float)k;

    // ---- pass 1: running max ----
    float m0 = -3.4e38f, m1 = -3.4e38f;
    #pragma unroll 1
    for (int j0 = 0; j0 < NPTS; j0 += 8) {
        const int q = j0 >> 1;
        #pragma unroll
        for (int k2 = 0; k2 < 4; k2++) {          // 4 x float4 = 8 columns
            float4 h = H4[q + k2];
            float a0 = fmai1(fmaf(xsc, h.x, h.y), du[2*k2]);
            float a1 = fmai1(fmaf(xsc, h.z, h.w), du[2*k2+1]);
            m0 = fmaxf(m0, a0);
            m1 = fmaxf(m1, a1);
        }
        #pragma unroll
        for (int k = 0; k < 8; k++) du[k] += u8;
    }
    const float m = fmaxf(m0, m1);
    const float negm = -m;

    // ---- pass 2: sum of exp2(A - m); -m folded into du ----
    #pragma unroll
    for (int k = 0; k < 8; k++) du[k] = fmaf(u, (float)k, negm);

    float s0 = 0.f, s1 = 0.f;
    #pragma unroll 1
    for (int j0 = 0; j0 < NPTS; j0 += 8) {
        const int q = j0 >> 1;
        #pragma unroll
        for (int k2 = 0; k2 < 4; k2++) {
            float4 h = H4[q + k2];
            float d0 = fmai1(fmaf(xsc, h.x, h.y), du[2*k2]);
            float d1 = fmai1(fmaf(xsc, h.z, h.w), du[2*k2+1]);
            float e0 = ex2f(d0);
            float e1 = ex2f(d1);
            s0 = fmai1(e0, s0);
            s1 = fmai1(e1, s1);
        }
        #pragma unroll
        for (int k = 0; k < 8; k++) du[k] += u8;
    }
    const float s = s0 + s1;

    float ti = (float)tid * DT_F;
    return fmaf(-eps * LN2_F, m + lg2f(s), 0.5f * (ti*ti + xi*xi));
}

__global__ void __launch_bounds__(256, 4)
sink_main(const float* __restrict__ syn, const float* __restrict__ obs,
          float* __restrict__ out)
{
    __shared__ SinkSmem sm;
    __shared__ bool sLast;
    const int p   = blockIdx.x;         // 0..511
    const int tid = threadIdx.x;        // row index 0..255
    const int bs  = p / NRECV;          // b*NS + s
    const int r   = p - bs * NRECV;

    const size_t base = (size_t)bs * NTIME * NRECV + r;
    const float xobs = obs[base + (size_t)tid * NRECV];
    const float xsyn = syn[base + (size_t)tid * NRECV];
    sm.xo[tid] = xobs;
    sm.xs[tid] = xsyn;
    sm.F[tid] = 0.f; sm.G[tid] = 0.f; sm.PX[tid] = 0.f; sm.PY[tid] = 0.f;
    __syncthreads();

    // trace mask + diameter
    float sabs_o = blockSum(fabsf(xobs), sm.red);
    float sabs_s = blockSum(fabsf(xsyn), sm.red);
    float vmax   = blockMax(fmaxf(xobs, xsyn), sm.red);
    float vmin   = blockMin(fminf(xobs, xsyn), sm.red);
    const bool masked = (sabs_o == 0.f) && (sabs_s == 0.f);

    const float trange   = (float)(NTIME - 1) * DT_F;
    const float diameter = fmaxf(trange, vmax - vmin);
    const float eps0     = diameter * diameter;           // P = 2
    const float la2      = -lg2f((float)NPTS);

    float fi = 0.f, gi = 0.f, pxi = 0.f, pyi = 0.f;
    float eps_raw = eps0;

    for (int k = 0; k < NSTEPS; k++) {
        const float eps = fmaxf(eps_raw, EPSMIN_F);
        eps_raw *= RATIO_F;
        const float ie2 = LOG2E_F / eps;
        const float c2  = 0.5f * DT_F * DT_F * ie2;

        // all four softmins read OLD potentials (scan-step semantics)
        fi  = softmin256(sm.G,  sm.xs, sm, xobs, ie2, c2, eps, la2);
        gi  = softmin256(sm.F,  sm.xo, sm, xsyn, ie2, c2, eps, la2);
        pxi = 0.5f * (pxi + softmin256(sm.PX, sm.xo, sm, xobs, ie2, c2, eps, la2));
        pyi = 0.5f * (pyi + softmin256(sm.PY, sm.xs, sm, xsyn, ie2, c2, eps, la2));

        __syncthreads();   // everyone done reading old potentials
        sm.F[tid] = fi; sm.G[tid] = gi; sm.PX[tid] = pxi; sm.PY[tid] = pyi;
    }
    __syncthreads();

    // S = sum w*(f - px) + sum w*(g - py), w = 1/n
    float contrib = (fi - pxi + gi - pyi) * (1.0f / (float)NPTS);
    float div = blockSum(contrib, sm.red);

    // ---- fused finalize: last-arriving block reduces g_div deterministically ----
    if (tid == 0) {
        g_div[p] = masked ? 0.f : div;
        __threadfence();
        unsigned int t = atomicAdd(&g_done, 1u);
        sLast = (t == NPROB - 1u);
    }
    __syncthreads();

    if (sLast) {
        // all 512 g_div writes are visible (their fences precede our winning ticket)
        const int perB = NS * NRECV;   // 256
        float v0 = g_div[tid];                 // batch 0
        float v1 = g_div[perB + tid];          // batch 1
        float o0 = blockSum(v0, sm.red);
        float o1 = blockSum(v1, sm.red);
        if (tid == 0) {
            out[0] = o0;
            out[1] = o1;
            g_done = 0;                        // reset ticket for next launch
        }
    }
}

extern "C" void kernel_launch(void* const* d_in, const int* in_sizes, int n_in,
                              void* d_out, int out_size)
{
    const float* syn = (const float*)d_in[0];   // syn_data [B,S,NT,NR]
    const float* obs = (const float*)d_in[1];   // obs_data [B,S,NT,NR]
    float* out = (float*)d_out;                 // [B] float32

    sink_main<<<NPROB, 256>>>(syn, obs, out);
}

// round 17
// speedup vs baseline: 1.6805x; 1.6805x over previous
#include <cuda_runtime.h>

// Problem constants (fixed shapes from reference setup_inputs)
#define NB 2
#define NS 4
#define NTIME 256
#define NRECV 64
#define NPROB (NB*NS*NRECV)   // 512 independent sinkhorn problems
#define NPTS  256             // points per cloud
#define NSTEPS 24

#define LOG2E_F 1.4426950408889634f
#define LN2_F   0.6931471805599453f
#define DT_F    0.001f
#define EPSMIN_F 1e-4f        // BLUR^2
#define RATIO_F 0.25f         // SCALING^2

__device__ float g_div[NPROB];          // per-problem divergence
__device__ unsigned int g_done = 0;     // last-block ticket (reset every launch)

__device__ __forceinline__ float ex2f(float x){ float y; asm("ex2.approx.ftz.f32 %0, %1;" : "=f"(y) : "f"(x)); return y; }
__device__ __forceinline__ float lg2f(float x){ float y; asm("lg2.approx.ftz.f32 %0, %1;" : "=f"(y) : "f"(x)); return y; }
// a*1.0 + c : FFMA with immediate multiplier (rt=1 form); rounding identical to FADD
__device__ __forceinline__ float fmai1(float a, float c){ float d; asm("fma.rn.f32 %0, %1, 0f3F800000, %2;" : "=f"(d) : "f"(a), "f"(c)); return d; }

struct SinkSmem {
    alignas(16) float2 hp[NPTS];   // (y_j, T_j) per column; 16B-aligned for LDS.128
    float  xo[NPTS];   // obs amplitudes
    float  xs[NPTS];   // syn amplitudes
    float  F[NPTS], G[NPTS], PX[NPTS], PY[NPTS];
    float  red[32];
};

__device__ __forceinline__ float warpSum(float v){
    #pragma unroll
    for (int o = 16; o; o >>= 1) v += __shfl_xor_sync(0xffffffffu, v, o);
    return v;
}
__device__ __forceinline__ float warpMax(float v){
    #pragma unroll
    for (int o = 16; o; o >>= 1) v = fmaxf(v, __shfl_xor_sync(0xffffffffu, v, o));
    return v;
}
__device__ __forceinline__ float warpMin(float v){
    #pragma unroll
    for (int o = 16; o; o >>= 1) v = fminf(v, __shfl_xor_sync(0xffffffffu, v, o));
    return v;
}

__device__ __forceinline__ float blockSum(float v, float* red){
    v = warpSum(v);
    int w = threadIdx.x >> 5, l = threadIdx.x & 31;
    if (l == 0) red[w] = v;
    __syncthreads();
    if (w == 0) {
        float t = (l < 8) ? red[l] : 0.f;
        t = warpSum(t);
        if (l == 0) red[0] = t;
    }
    __syncthreads();
    v = red[0];
    __syncthreads();
    return v;
}
__device__ __forceinline__ float blockMax(float v, float* red){
    v = warpMax(v);
    int w = threadIdx.x >> 5, l = threadIdx.x & 31;
    if (l == 0) red[w] = v;
    __syncthreads();
    if (w == 0) {
        float t = (l < 8) ? red[l] : -3.4e38f;
        t = warpMax(t);
        if (l == 0) red[0] = t;
    }
    __syncthreads();
    v = red[0];
    __syncthreads();
    return v;
}
__device__ __forceinline__ float blockMin(float v, float* red){
    v = warpMin(v);
    int w = threadIdx.x >> 5, l = threadIdx.x & 31;
    if (l == 0) red[w] = v;
    __syncthreads();
    if (w == 0) {
        float t = (l < 8) ? red[l] : 3.4e38f;
        t = warpMin(t);
        if (l == 0) red[0] = t;
    }
    __syncthreads();
    v = red[0];
    __syncthreads();
    return v;
}

// softmin over 256 columns, log2 domain:
// A_ij = T_j + xsc*y_j + u*j + C_i
//   T_j = la2 + pot_j*ie2 - 0.5*ie2*y_j^2 - c2*j^2   (smem float2 with y_j)
//   xsc = xi*ie2, u = 2*c2*i;  C_i folds back as +0.5*||X_i||^2 in the result.
// Inner loops: one LDS.128 per column pair; u*j carried by two counters uj0/uj1
// stepping 2u; pass 2 folds -m into the counters, rebased every 8 columns so the
// rounding on the large |m| base never accumulates more than 3 adds.
__device__ __forceinline__ float softmin256(
    const float* __restrict__ pot, const float* __restrict__ yc,
    SinkSmem& sm,
    float xi, float ie2, float c2, float eps, float la2)
{
    const int tid = threadIdx.x;
    __syncthreads();  // previous users of hp are done
    {
        float yv = yc[tid];
        float jv = (float)tid;
        float t  = la2 + pot[tid]*ie2 - (0.5f*yv*yv)*ie2 - c2*jv*jv;
        sm.hp[tid] = make_float2(yv, t);
    }
    __syncthreads();

    const float xsc = xi * ie2;
    const float u   = 2.0f * c2 * (float)tid;
    const float u2  = u + u;
    const float4* __restrict__ H4 = (const float4*)sm.hp;  // (y0,T0,y1,T1)

    // ---- pass 1: running max ----
    float m0 = -3.4e38f, m1 = -3.4e38f;
    float uj0 = 0.f, uj1 = u;
    #pragma unroll 4
    for (int q = 0; q < NPTS/2; q++) {
        float4 h = H4[q];
        float c0 = fmaf(xsc, h.x, h.y);
        float c1 = fmaf(xsc, h.z, h.w);
        m0 = fmaxf(m0, fmai1(c0, uj0));
        m1 = fmaxf(m1, fmai1(c1, uj1));
        uj0 += u2; uj1 += u2;
    }
    const float m = fmaxf(m0, m1);
    const float negm = -m;

    // ---- pass 2: sum of exp2(A - m); -m folded into counters, rebased per 8 ----
    float s0 = 0.f, s1 = 0.f;
    #pragma unroll 1
    for (int j0 = 0; j0 < NPTS; j0 += 8) {
        float v0 = fmaf(u, (float)j0, negm);   // fresh base: no long drift on |m|
        float v1 = v0 + u;
        #pragma unroll
        for (int k = 0; k < 4; k++) {
            float4 h = H4[(j0 >> 1) + k];
            float c0 = fmaf(xsc, h.x, h.y);
            float c1 = fmaf(xsc, h.z, h.w);
            s0 = fmai1(ex2f(fmai1(c0, v0)), s0);
            s1 = fmai1(ex2f(fmai1(c1, v1)), s1);
            if (k < 3) { v0 += u2; v1 += u2; }
        }
    }
    const float s = s0 + s1;

    float ti = (float)tid * DT_F;
    return fmaf(-eps * LN2_F, m + lg2f(s), 0.5f * (ti*ti + xi*xi));
}

__global__ void __launch_bounds__(256, 4)
sink_main(const float* __restrict__ syn, const float* __restrict__ obs,
          float* __restrict__ out)
{
    __shared__ SinkSmem sm;
    __shared__ bool sLast;
    const int p   = blockIdx.x;         // 0..511
    const int tid = threadIdx.x;        // row index 0..255
    const int bs  = p / NRECV;          // b*NS + s
    const int r   = p - bs * NRECV;

    const size_t base = (size_t)bs * NTIME * NRECV + r;
    const float xobs = obs[base + (size_t)tid * NRECV];
    const float xsyn = syn[base + (size_t)tid * NRECV];
    sm.xo[tid] = xobs;
    sm.xs[tid] = xsyn;
    sm.F[tid] = 0.f; sm.G[tid] = 0.f; sm.PX[tid] = 0.f; sm.PY[tid] = 0.f;
    __syncthreads();

    // trace mask + diameter
    float sabs_o = blockSum(fabsf(xobs), sm.red);
    float sabs_s = blockSum(fabsf(xsyn), sm.red);
    float vmax   = blockMax(fmaxf(xobs, xsyn), sm.red);
    float vmin   = blockMin(fminf(xobs, xsyn), sm.red);
    const bool masked = (sabs_o == 0.f) && (sabs_s == 0.f);

    const float trange   = (float)(NTIME - 1) * DT_F;
    const float diameter = fmaxf(trange, vmax - vmin);
    const float eps0     = diameter * diameter;           // P = 2
    const float la2      = -lg2f((float)NPTS);

    float fi = 0.f, gi = 0.f, pxi = 0.f, pyi = 0.f;
    float eps_raw = eps0;

    for (int k = 0; k < NSTEPS; k++) {
        const float eps = fmaxf(eps_raw, EPSMIN_F);
        eps_raw *= RATIO_F;
        const float ie2 = LOG2E_F / eps;
        const float c2  = 0.5f * DT_F * DT_F * ie2;

        // all four softmins read OLD potentials (scan-step semantics)
        fi  = softmin256(sm.G,  sm.xs, sm, xobs, ie2, c2, eps, la2);
        gi  = softmin256(sm.F,  sm.xo, sm, xsyn, ie2, c2, eps, la2);
        pxi = 0.5f * (pxi + softmin256(sm.PX, sm.xo, sm, xobs, ie2, c2, eps, la2));
        pyi = 0.5f * (pyi + softmin256(sm.PY, sm.xs, sm, xsyn, ie2, c2, eps, la2));

        __syncthreads();   // everyone done reading old potentials
        sm.F[tid] = fi; sm.G[tid] = gi; sm.PX[tid] = pxi; sm.PY[tid] = pyi;
    }
    __syncthreads();

    // S = sum w*(f - px) + sum w*(g - py), w = 1/n
    float contrib = (fi - pxi + gi - pyi) * (1.0f / (float)NPTS);
    float div = blockSum(contrib, sm.red);

    // ---- fused finalize: last-arriving block reduces g_div deterministically ----
    if (tid == 0) {
        g_div[p] = masked ? 0.f : div;
        __threadfence();
        unsigned int t = atomicAdd(&g_done, 1u);
        sLast = (t == NPROB - 1u);
    }
    __syncthreads();

    if (sLast) {
        // all 512 g_div writes are visible (their fences precede our winning ticket)
        const int perB = NS * NRECV;   // 256
        float v0 = g_div[tid];                 // batch 0
        float v1 = g_div[perB + tid];          // batch 1
        float o0 = blockSum(v0, sm.red);
        float o1 = blockSum(v1, sm.red);
        if (tid == 0) {
            out[0] = o0;
            out[1] = o1;
            g_done = 0;                        // reset ticket for next launch
        }
    }
}

extern "C" void kernel_launch(void* const* d_in, const int* in_sizes, int n_in,
                              void* d_out, int out_size)
{
    const float* syn = (const float*)d_in[0];   // syn_data [B,S,NT,NR]
    const float* obs = (const float*)d_in[1];   // obs_data [B,S,NT,NR]
    float* out = (float*)d_out;                 // [B] float32

    sink_main<<<NPROB, 256>>>(syn, obs, out);
}